// round 9
// baseline (speedup 1.0000x reference)
#include <cuda_runtime.h>
#include <cuda_bf16.h>
#include <cstdint>

#define NN 50000
#define NE 800000

// ---------------- scratch (static device globals; no allocation) ----------------
__device__ float g_H1[(size_t)NN * 256];    // layer1 projected features
__device__ float g_H2p[(size_t)NN * 128];   // layer2 projected features
__device__ int   g_deg_out[NN];
__device__ int   g_deg_in[NN];
__device__ float g_ns[NN];
__device__ float g_nd[NN];
__device__ int   g_rowptr[NN + 1];
__device__ int   g_cursor[NN];
__device__ int   g_csrc[NE];
__device__ int   g_is64;

// pre-split A operands, fragment-packed:
// element (r, ks, q) = uint4{ hi(2q,2q+1), hi(2q+8,2q+9), lo(2q,2q+1), lo(2q+8,2q+9) }
// of row r, k-block ks (k = ks*16 + local). Index: (r*16 + ks)*4 + q.
__device__ uint4 g_xp[(size_t)NN * 64];     // layer1 A = x * ns  (split)
__device__ uint4 g_h2p2[(size_t)NN * 64];   // layer2 A = relu(conv1) * ns (split)

// weight fragment packs: uint2{hi_pair, lo_pair} indexed
// ((ks*NT8 + nt8)*2 + breg)*32 + lane
__device__ uint2 g_B1p[16 * 32 * 2 * 32];   // W1: Nt=256, NT8=32
__device__ uint2 g_B2p[16 * 16 * 2 * 32];   // W2: Nt=128, NT8=16

// bf16 hi/lo split of two fp32, packed as bf16x2
__device__ __forceinline__ uint2 split_pack(float f0, float f1) {
    __nv_bfloat16 h0 = __float2bfloat16(f0), h1 = __float2bfloat16(f1);
    float l0 = f0 - __bfloat162float(h0);
    float l1 = f1 - __bfloat162float(h1);
    __nv_bfloat16 g0 = __float2bfloat16(l0), g1 = __float2bfloat16(l1);
    uint2 r;
    r.x = (uint32_t)__bfloat16_as_ushort(h0) | ((uint32_t)__bfloat16_as_ushort(h1) << 16);
    r.y = (uint32_t)__bfloat16_as_ushort(g0) | ((uint32_t)__bfloat16_as_ushort(g1) << 16);
    return r;
}

__device__ __forceinline__ void mma_bf16(float* c, const uint32_t* a, uint32_t b0, uint32_t b1) {
    asm volatile(
        "mma.sync.aligned.m16n8k16.row.col.f32.bf16.bf16.f32 "
        "{%0,%1,%2,%3}, {%4,%5,%6,%7}, {%8,%9}, {%0,%1,%2,%3};"
        : "+f"(c[0]), "+f"(c[1]), "+f"(c[2]), "+f"(c[3])
        : "r"(a[0]), "r"(a[1]), "r"(a[2]), "r"(a[3]), "r"(b0), "r"(b1));
}

// ---------------- edge index accessor (dtype-robust) ----------------
__device__ __forceinline__ int edge_at(const void* p, int i, int is64) {
    if (is64) return (int)((const long long*)p)[i];
    return ((const int*)p)[i];
}

__global__ void k_detect(const int* __restrict__ src_as_i32) {
    if (threadIdx.x == 0) {
        int allzero = 1;
        for (int i = 0; i < 256; i++)
            if (src_as_i32[2 * i + 1] != 0) { allzero = 0; break; }
        g_is64 = allzero;
    }
}

// ---------------- graph prep ----------------
__global__ void k_zero() {
    int i = blockIdx.x * 256 + threadIdx.x;
    if (i < NN) { g_deg_out[i] = 0; g_deg_in[i] = 0; g_cursor[i] = 0; }
}

__global__ void k_degree(const void* __restrict__ src, const void* __restrict__ dst) {
    int e = blockIdx.x * 256 + threadIdx.x;
    if (e < NE) {
        int is64 = g_is64;
        unsigned s = (unsigned)edge_at(src, e, is64);
        unsigned d = (unsigned)edge_at(dst, e, is64);
        if (s < NN) atomicAdd(&g_deg_out[s], 1);
        if (d < NN) atomicAdd(&g_deg_in[d], 1);
    }
}

__global__ void k_norm() {
    int i = blockIdx.x * 256 + threadIdx.x;
    if (i < NN) {
        int a = g_deg_out[i]; if (a < 1) a = 1;
        int b = g_deg_in[i];  if (b < 1) b = 1;
        g_ns[i] = rsqrtf((float)a);
        g_nd[i] = rsqrtf((float)b);
    }
}

__global__ void k_scan() {
    __shared__ int sh[1024];
    const int CH = (NN + 1023) / 1024;
    int tid = threadIdx.x;
    int st = tid * CH;
    int en = st + CH; if (en > NN) en = NN;
    int s = 0;
    for (int j = st; j < en; ++j) s += g_deg_in[j];
    sh[tid] = s;
    __syncthreads();
    for (int off = 1; off < 1024; off <<= 1) {
        int v = 0;
        if (tid >= off) v = sh[tid - off];
        __syncthreads();
        sh[tid] += v;
        __syncthreads();
    }
    int run = sh[tid] - s;
    for (int j = st; j < en; ++j) { g_rowptr[j] = run; run += g_deg_in[j]; }
    if (tid == 1023) g_rowptr[NN] = sh[1023];
}

__global__ void k_csr(const void* __restrict__ src, const void* __restrict__ dst) {
    int e = blockIdx.x * 256 + threadIdx.x;
    if (e < NE) {
        int is64 = g_is64;
        unsigned s = (unsigned)edge_at(src, e, is64);
        unsigned d = (unsigned)edge_at(dst, e, is64);
        if (s < NN && d < NN) {
            int pos = atomicAdd(&g_cursor[d], 1);
            int slot = g_rowptr[d] + pos;
            if (slot < NE) g_csrc[slot] = (int)s;
        }
    }
}

// ---------------- x -> pre-split packed A (norm_src folded in) ----------------
__global__ void k_xsplit(const float* __restrict__ x) {
    int idx = blockIdx.x * 256 + threadIdx.x;   // over NN*64
    if (idx >= NN * 64) return;
    int r = idx >> 6;
    int ks = (idx >> 2) & 15;
    int q = idx & 3;
    const float* ap = x + (size_t)r * 256 + ks * 16 + q * 2;
    float s = g_ns[r];
    float2 v0 = *(const float2*)ap;
    float2 v1 = *(const float2*)(ap + 8);
    v0.x *= s; v0.y *= s; v1.x *= s; v1.y *= s;
    uint2 p0 = split_pack(v0.x, v0.y);
    uint2 p1 = split_pack(v1.x, v1.y);
    g_xp[idx] = make_uint4(p0.x, p1.x, p0.y, p1.y);
}

// ---------------- weight -> fragment-order bf16 hi/lo pack ----------------
template <bool L1>
__global__ void k_wpack(const float* __restrict__ W) {
    constexpr int Nt = L1 ? 256 : 128;
    constexpr int NT8 = Nt >> 3;
    uint2* out = L1 ? g_B1p : g_B2p;
    int total = 16 * NT8 * 2 * 32;
    int idx = blockIdx.x * 256 + threadIdx.x;
    if (idx >= total) return;
    int lane = idx & 31;
    int breg = (idx >> 5) & 1;
    int rest = idx >> 6;                  // ks*NT8 + nt8
    int nt8 = rest % NT8;
    int ks = rest / NT8;
    int k = ks * 16 + (lane & 3) * 2 + breg * 8;
    int n = nt8 * 8 + (lane >> 2);
    float w0 = W[(size_t)k * Nt + n];
    float w1 = W[(size_t)(k + 1) * Nt + n];
    out[idx] = split_pack(w0, w1);
}

// ---------------- MMA GEMM: C[128 x Nt-tile] = Apre @ W, 3x bf16 split ----------
// 256 threads = 8 warps (4M x 2N); warp tile 32x64; no shared memory.
// A comes pre-split & pre-scaled from g_xp / g_h2p2 (one LDG.128 per row/kstep).
template <bool L1>
__global__ void __launch_bounds__(256, 1) k_mma() {
    constexpr int Nt = L1 ? 256 : 128;
    constexpr int NT8 = Nt >> 3;
    const uint4* Ap = L1 ? g_xp : g_h2p2;
    float* C = L1 ? g_H1 : g_H2p;
    const uint2* Bp = L1 ? g_B1p : g_B2p;

    int tid = threadIdx.x;
    int wid = tid >> 5, lid = tid & 31;
    int wm = wid >> 1, wn = wid & 1;
    int g = lid >> 2, q = lid & 3;
    int brow = blockIdx.x * 128;
    int bcol = blockIdx.y * 128;

    int rbase = brow + wm * 32 + g;
    int rows[4] = {rbase, rbase + 8, rbase + 16, rbase + 24};
    bool valid[4];
#pragma unroll
    for (int i = 0; i < 4; i++) valid[i] = rows[i] < NN;

    float acc[2][8][4];
#pragma unroll
    for (int mt = 0; mt < 2; mt++)
#pragma unroll
        for (int j = 0; j < 8; j++)
#pragma unroll
            for (int c = 0; c < 4; c++) acc[mt][j][c] = 0.f;

    const uint2* bbase = Bp + (size_t)((bcol >> 3) + wn * 8) * 64 + lid;

    for (int ks = 0; ks < 16; ks++) {
        // ---- A fragments: one 16B load per row per kstep ----
        uint32_t ah[2][4], al[2][4];
#pragma unroll
        for (int ri = 0; ri < 4; ri++) {
            uint4 v = make_uint4(0u, 0u, 0u, 0u);
            if (valid[ri]) v = Ap[((size_t)rows[ri] * 16 + ks) * 4 + q];
            int mt = ri >> 1, half = ri & 1;
            ah[mt][half] = v.x;
            ah[mt][half + 2] = v.y;
            al[mt][half] = v.z;
            al[mt][half + 2] = v.w;
        }
        // ---- B fragments (pre-packed, coalesced) ----
        const uint2* bk = bbase + (size_t)ks * NT8 * 64;
        uint2 b0[8], b1[8];
#pragma unroll
        for (int j = 0; j < 8; j++) {
            b0[j] = bk[j * 64];
            b1[j] = bk[j * 64 + 32];
        }
        // ---- MMAs: AhBh + AhBl + AlBh ----
#pragma unroll
        for (int mt = 0; mt < 2; mt++)
#pragma unroll
            for (int j = 0; j < 8; j++) {
                mma_bf16(acc[mt][j], ah[mt], b0[j].x, b1[j].x);
                mma_bf16(acc[mt][j], ah[mt], b0[j].y, b1[j].y);
                mma_bf16(acc[mt][j], al[mt], b0[j].x, b1[j].x);
            }
    }

    // ---- epilogue ----
    int cb = bcol + wn * 64 + q * 2;
#pragma unroll
    for (int mt = 0; mt < 2; mt++) {
        int r0 = rows[mt * 2], r1 = rows[mt * 2 + 1];
#pragma unroll
        for (int j = 0; j < 8; j++) {
            if (valid[mt * 2])
                *(float2*)(C + (size_t)r0 * Nt + cb + j * 8) =
                    make_float2(acc[mt][j][0], acc[mt][j][1]);
            if (valid[mt * 2 + 1])
                *(float2*)(C + (size_t)r1 * Nt + cb + j * 8) =
                    make_float2(acc[mt][j][2], acc[mt][j][3]);
        }
    }
}

// ---------------- aggregation layer 1: gather-sum, emit pre-split packed ----------
__global__ void k_agg1(const float* __restrict__ b1) {
    int node = blockIdx.x * blockDim.y + threadIdx.y;
    if (node >= NN) return;
    int f = threadIdx.x;  // 0..63 float4 lanes (cols 4f..4f+3)
    const float4* H = (const float4*)g_H1;
    int beg = g_rowptr[node], end = g_rowptr[node + 1];

    float4 a = make_float4(0.f, 0.f, 0.f, 0.f);
    float4 b = make_float4(0.f, 0.f, 0.f, 0.f);
    int e = beg;
    for (; e + 4 <= end; e += 4) {
        int s0 = g_csrc[e], s1 = g_csrc[e + 1], s2 = g_csrc[e + 2], s3 = g_csrc[e + 3];
        float4 v0 = H[(size_t)s0 * 64 + f];
        float4 v1 = H[(size_t)s1 * 64 + f];
        float4 v2 = H[(size_t)s2 * 64 + f];
        float4 v3 = H[(size_t)s3 * 64 + f];
        a.x += v0.x; a.y += v0.y; a.z += v0.z; a.w += v0.w;
        b.x += v1.x; b.y += v1.y; b.z += v1.z; b.w += v1.w;
        a.x += v2.x; a.y += v2.y; a.z += v2.z; a.w += v2.w;
        b.x += v3.x; b.y += v3.y; b.z += v3.z; b.w += v3.w;
    }
    for (; e < end; e++) {
        int s = g_csrc[e];
        float4 v = H[(size_t)s * 64 + f];
        a.x += v.x; a.y += v.y; a.z += v.z; a.w += v.w;
    }
    float nd = g_nd[node], ns = g_ns[node];
    float4 bb = ((const float4*)b1)[f];
    float4 r;
    r.x = fmaxf(fmaf(a.x + b.x, nd, bb.x), 0.f) * ns;
    r.y = fmaxf(fmaf(a.y + b.y, nd, bb.y), 0.f) * ns;
    r.z = fmaxf(fmaf(a.z + b.z, nd, bb.z), 0.f) * ns;
    r.w = fmaxf(fmaf(a.w + b.w, nd, bb.w), 0.f) * ns;

    // write pre-split packed form for the layer-2 GEMM.
    // pair p covers cols (2p, 2p+1); p0 = 2f (r.x,r.y), p1 = 2f+1 (r.z,r.w).
    uint32_t* o = (uint32_t*)g_h2p2;
    {
        uint2 ph = split_pack(r.x, r.y);
        int p = 2 * f, ks = p >> 3, qq = p & 7;
        size_t base = (((size_t)node * 16 + ks) * 4 + (qq & 3)) * 4;
        o[base + (qq >> 2)] = ph.x;
        o[base + 2 + (qq >> 2)] = ph.y;
    }
    {
        uint2 ph = split_pack(r.z, r.w);
        int p = 2 * f + 1, ks = p >> 3, qq = p & 7;
        size_t base = (((size_t)node * 16 + ks) * 4 + (qq & 3)) * 4;
        o[base + (qq >> 2)] = ph.x;
        o[base + 2 + (qq >> 2)] = ph.y;
    }
}

// ---------------- aggregation layer 2 ----------------
__global__ void k_agg2(const float* __restrict__ b2, float* __restrict__ out) {
    int node = blockIdx.x * blockDim.y + threadIdx.y;
    if (node >= NN) return;
    int f = threadIdx.x;  // 0..31 float4 lanes
    const float4* H = (const float4*)g_H2p;
    int beg = g_rowptr[node], end = g_rowptr[node + 1];

    float4 a = make_float4(0.f, 0.f, 0.f, 0.f);
    float4 b = make_float4(0.f, 0.f, 0.f, 0.f);
    int e = beg;
    for (; e + 4 <= end; e += 4) {
        int s0 = g_csrc[e], s1 = g_csrc[e + 1], s2 = g_csrc[e + 2], s3 = g_csrc[e + 3];
        float4 v0 = H[(size_t)s0 * 32 + f];
        float4 v1 = H[(size_t)s1 * 32 + f];
        float4 v2 = H[(size_t)s2 * 32 + f];
        float4 v3 = H[(size_t)s3 * 32 + f];
        a.x += v0.x; a.y += v0.y; a.z += v0.z; a.w += v0.w;
        b.x += v1.x; b.y += v1.y; b.z += v1.z; b.w += v1.w;
        a.x += v2.x; a.y += v2.y; a.z += v2.z; a.w += v2.w;
        b.x += v3.x; b.y += v3.y; b.z += v3.z; b.w += v3.w;
    }
    for (; e < end; e++) {
        int s = g_csrc[e];
        float4 v = H[(size_t)s * 32 + f];
        a.x += v.x; a.y += v.y; a.z += v.z; a.w += v.w;
    }
    float nd = g_nd[node];
    float4 bb = ((const float4*)b2)[f];
    float4 r;
    r.x = fmaf(a.x + b.x, nd, bb.x);
    r.y = fmaf(a.y + b.y, nd, bb.y);
    r.z = fmaf(a.z + b.z, nd, bb.z);
    r.w = fmaf(a.w + b.w, nd, bb.w);
    ((float4*)out)[(size_t)node * 32 + f] = r;
}

// ---------------- launch ----------------
extern "C" void kernel_launch(void* const* d_in, const int* in_sizes, int n_in,
                              void* d_out, int out_size) {
    const float* x   = (const float*)d_in[0];
    const void*  src = d_in[1];
    const void*  dst = d_in[2];
    const float* W1  = (const float*)d_in[3];
    const float* b1  = (const float*)d_in[4];
    const float* W2  = (const float*)d_in[5];
    const float* b2  = (const float*)d_in[6];
    float* out = (float*)d_out;

    k_detect<<<1, 32>>>((const int*)src);
    k_zero<<<(NN + 255) / 256, 256>>>();
    k_degree<<<(NE + 255) / 256, 256>>>(src, dst);
    k_norm<<<(NN + 255) / 256, 256>>>();
    k_scan<<<1, 1024>>>();
    k_csr<<<(NE + 255) / 256, 256>>>(src, dst);
    k_wpack<true><<<128, 256>>>(W1);
    k_wpack<false><<<64, 256>>>(W2);
    k_xsplit<<<(NN * 64 + 255) / 256, 256>>>(x);

    const int GB = (NN + 127) / 128;  // 391
    k_mma<true><<<dim3(GB, 2), 256>>>();
    k_agg1<<<(NN + 3) / 4, dim3(64, 4)>>>(b1);
    k_mma<false><<<dim3(GB, 1), 256>>>();
    k_agg2<<<(NN + 7) / 8, dim3(32, 8)>>>(b2, out);
}

// round 10
// speedup vs baseline: 1.1777x; 1.1777x over previous
#include <cuda_runtime.h>
#include <cuda_fp16.h>
#include <cstdint>

#define NN 50000
#define NE 800000

// ---------------- scratch (static device globals; no allocation) ----------------
__device__ int   g_deg_out[NN];
__device__ int   g_deg_in[NN];
__device__ float g_ns[NN];
__device__ float g_nd[NN];
__device__ int   g_rowptr[NN + 1];
__device__ int   g_cursor[NN];
__device__ int   g_csrc[NE];
__device__ int   g_is64;

// fragment-packed f16 A operands:
// uint2 element (r, ks, q) = { f16pair(cols ks*16+2q, +1), f16pair(cols ks*16+2q+8, +9) }
// linear index (r*16 + ks)*4 + q
__device__ uint2 g_A1p[(size_t)NN * 64];    // layer1 A = x * ns      (f16)
__device__ uint2 g_A2p[(size_t)NN * 64];    // layer2 A = relu(conv1)*ns (f16)

// f16 feature stores for aggregation gathers
__device__ uint4 g_H1h[(size_t)NN * 32];    // H1  [NN,256] f16
__device__ uint2 g_H2h[(size_t)NN * 32];    // H2p [NN,128] f16

// weight fragment packs (f16 hi/lo): uint2{hi_pair, lo_pair},
// index ((ks*NT8 + nt8)*2 + breg)*32 + lane
__device__ uint2 g_B1p[16 * 32 * 2 * 32];   // W1: Nt=256
__device__ uint2 g_B2p[16 * 16 * 2 * 32];   // W2: Nt=128

// ---------------- small helpers ----------------
__device__ __forceinline__ uint32_t h2u(__half2 h) {
    return *reinterpret_cast<uint32_t*>(&h);
}
__device__ __forceinline__ float2 u2f2(uint32_t u) {
    __half2 h = *reinterpret_cast<__half2*>(&u);
    return __half22float2(h);
}
// f16 hi/lo split of two fp32: {hi_pair, lo_pair}
__device__ __forceinline__ uint2 split_pack_h(float f0, float f1) {
    __half h0 = __float2half_rn(f0), h1 = __float2half_rn(f1);
    __half l0 = __float2half_rn(f0 - __half2float(h0));
    __half l1 = __float2half_rn(f1 - __half2float(h1));
    uint2 r;
    r.x = (uint32_t)__half_as_ushort(h0) | ((uint32_t)__half_as_ushort(h1) << 16);
    r.y = (uint32_t)__half_as_ushort(l0) | ((uint32_t)__half_as_ushort(l1) << 16);
    return r;
}

__device__ __forceinline__ void mma_f16(float* c, const uint32_t* a, uint32_t b0, uint32_t b1) {
    asm volatile(
        "mma.sync.aligned.m16n8k16.row.col.f32.f16.f16.f32 "
        "{%0,%1,%2,%3}, {%4,%5,%6,%7}, {%8,%9}, {%0,%1,%2,%3};"
        : "+f"(c[0]), "+f"(c[1]), "+f"(c[2]), "+f"(c[3])
        : "r"(a[0]), "r"(a[1]), "r"(a[2]), "r"(a[3]), "r"(b0), "r"(b1));
}

// ---------------- edge index accessor (dtype-robust) ----------------
__device__ __forceinline__ int edge_at(const void* p, int i, int is64) {
    if (is64) return (int)((const long long*)p)[i];
    return ((const int*)p)[i];
}

__global__ void k_detect(const int* __restrict__ src_as_i32) {
    if (threadIdx.x == 0) {
        int allzero = 1;
        for (int i = 0; i < 256; i++)
            if (src_as_i32[2 * i + 1] != 0) { allzero = 0; break; }
        g_is64 = allzero;
    }
}

// ---------------- graph prep ----------------
__global__ void k_zero() {
    int i = blockIdx.x * 256 + threadIdx.x;
    if (i < NN) { g_deg_out[i] = 0; g_deg_in[i] = 0; g_cursor[i] = 0; }
}

__global__ void k_degree(const void* __restrict__ src, const void* __restrict__ dst) {
    int e = blockIdx.x * 256 + threadIdx.x;
    if (e < NE) {
        int is64 = g_is64;
        unsigned s = (unsigned)edge_at(src, e, is64);
        unsigned d = (unsigned)edge_at(dst, e, is64);
        if (s < NN) atomicAdd(&g_deg_out[s], 1);
        if (d < NN) atomicAdd(&g_deg_in[d], 1);
    }
}

__global__ void k_norm() {
    int i = blockIdx.x * 256 + threadIdx.x;
    if (i < NN) {
        int a = g_deg_out[i]; if (a < 1) a = 1;
        int b = g_deg_in[i];  if (b < 1) b = 1;
        g_ns[i] = rsqrtf((float)a);
        g_nd[i] = rsqrtf((float)b);
    }
}

__global__ void k_scan() {
    __shared__ int sh[1024];
    const int CH = (NN + 1023) / 1024;
    int tid = threadIdx.x;
    int st = tid * CH;
    int en = st + CH; if (en > NN) en = NN;
    int s = 0;
    for (int j = st; j < en; ++j) s += g_deg_in[j];
    sh[tid] = s;
    __syncthreads();
    for (int off = 1; off < 1024; off <<= 1) {
        int v = 0;
        if (tid >= off) v = sh[tid - off];
        __syncthreads();
        sh[tid] += v;
        __syncthreads();
    }
    int run = sh[tid] - s;
    for (int j = st; j < en; ++j) { g_rowptr[j] = run; run += g_deg_in[j]; }
    if (tid == 1023) g_rowptr[NN] = sh[1023];
}

__global__ void k_csr(const void* __restrict__ src, const void* __restrict__ dst) {
    int e = blockIdx.x * 256 + threadIdx.x;
    if (e < NE) {
        int is64 = g_is64;
        unsigned s = (unsigned)edge_at(src, e, is64);
        unsigned d = (unsigned)edge_at(dst, e, is64);
        if (s < NN && d < NN) {
            int pos = atomicAdd(&g_cursor[d], 1);
            int slot = g_rowptr[d] + pos;
            if (slot < NE) g_csrc[slot] = (int)s;
        }
    }
}

// ---------------- x -> fragment-packed f16 A1 (norm_src folded in) ----------------
__global__ void k_apack(const float* __restrict__ x) {
    int idx = blockIdx.x * 256 + threadIdx.x;   // over NN*64
    if (idx >= NN * 64) return;
    int r = idx >> 6;
    int ks = (idx >> 2) & 15;
    int q = idx & 3;
    const float* ap = x + (size_t)r * 256 + ks * 16 + q * 2;
    float s = g_ns[r];
    float2 v0 = *(const float2*)ap;
    float2 v1 = *(const float2*)(ap + 8);
    uint2 o;
    o.x = h2u(__floats2half2_rn(v0.x * s, v0.y * s));
    o.y = h2u(__floats2half2_rn(v1.x * s, v1.y * s));
    g_A1p[idx] = o;
}

// ---------------- weight -> fragment-order f16 hi/lo pack ----------------
template <bool L1>
__global__ void k_wpack(const float* __restrict__ W) {
    constexpr int Nt = L1 ? 256 : 128;
    constexpr int NT8 = Nt >> 3;
    uint2* out = L1 ? g_B1p : g_B2p;
    int total = 16 * NT8 * 2 * 32;
    int idx = blockIdx.x * 256 + threadIdx.x;
    if (idx >= total) return;
    int lane = idx & 31;
    int breg = (idx >> 5) & 1;
    int rest = idx >> 6;                  // ks*NT8 + nt8
    int nt8 = rest % NT8;
    int ks = rest / NT8;
    int k = ks * 16 + (lane & 3) * 2 + breg * 8;
    int n = nt8 * 8 + (lane >> 2);
    float w0 = W[(size_t)k * Nt + n];
    float w1 = W[(size_t)(k + 1) * Nt + n];
    out[idx] = split_pack_h(w0, w1);
}

// ---------------- MMA GEMM: H[128 x Nt] (f16 out) = Apack @ (Wh + Wl) -----------
// 256 threads = 8 warps (4M x 2N); warp tile 32x64; 2 MMAs per (mt,j) per kstep.
template <bool L1>
__global__ void __launch_bounds__(256) k_mma() {
    constexpr int Nt = L1 ? 256 : 128;
    constexpr int NT8 = Nt >> 3;
    const uint2* Ap = L1 ? g_A1p : g_A2p;
    uint32_t* Ch = L1 ? (uint32_t*)g_H1h : (uint32_t*)g_H2h;
    const uint2* Bp = L1 ? g_B1p : g_B2p;

    int tid = threadIdx.x;
    int wid = tid >> 5, lid = tid & 31;
    int wm = wid >> 1, wn = wid & 1;
    int g = lid >> 2, q = lid & 3;
    int brow = blockIdx.x * 128;
    int bcol = blockIdx.y * 128;

    int rbase = brow + wm * 32 + g;
    int rows[4] = {rbase, rbase + 8, rbase + 16, rbase + 24};
    bool valid[4];
#pragma unroll
    for (int i = 0; i < 4; i++) valid[i] = rows[i] < NN;

    float acc[2][8][4];
#pragma unroll
    for (int mt = 0; mt < 2; mt++)
#pragma unroll
        for (int j = 0; j < 8; j++)
#pragma unroll
            for (int c = 0; c < 4; c++) acc[mt][j][c] = 0.f;

    const uint2* bbase = Bp + (size_t)((bcol >> 3) + wn * 8) * 64 + lid;

    for (int ks = 0; ks < 16; ks++) {
        // ---- A fragments: one 8B load per row per kstep ----
        uint32_t a[2][4];
#pragma unroll
        for (int ri = 0; ri < 4; ri++) {
            uint2 v = make_uint2(0u, 0u);
            if (valid[ri]) v = Ap[((size_t)rows[ri] * 16 + ks) * 4 + q];
            int mt = ri >> 1, half = ri & 1;
            a[mt][half] = v.x;
            a[mt][half + 2] = v.y;
        }
        // ---- B fragments (pre-packed hi/lo) ----
        const uint2* bk = bbase + (size_t)ks * NT8 * 64;
        uint2 b0[8], b1[8];
#pragma unroll
        for (int j = 0; j < 8; j++) {
            b0[j] = bk[j * 64];
            b1[j] = bk[j * 64 + 32];
        }
        // ---- MMAs: A@Wh + A@Wl ----
#pragma unroll
        for (int mt = 0; mt < 2; mt++)
#pragma unroll
            for (int j = 0; j < 8; j++) {
                mma_f16(acc[mt][j], a[mt], b0[j].x, b1[j].x);
                mma_f16(acc[mt][j], a[mt], b0[j].y, b1[j].y);
            }
    }

    // ---- epilogue: write f16 pairs ----
    int cb = bcol + wn * 64 + q * 2;
#pragma unroll
    for (int mt = 0; mt < 2; mt++) {
        int r0 = rows[mt * 2], r1 = rows[mt * 2 + 1];
#pragma unroll
        for (int j = 0; j < 8; j++) {
            int ci = (cb + j * 8) >> 1;
            if (valid[mt * 2])
                Ch[(size_t)r0 * (Nt / 2) + ci] = h2u(__floats2half2_rn(acc[mt][j][0], acc[mt][j][1]));
            if (valid[mt * 2 + 1])
                Ch[(size_t)r1 * (Nt / 2) + ci] = h2u(__floats2half2_rn(acc[mt][j][2], acc[mt][j][3]));
        }
    }
}

// ---------------- aggregation layer 1 (f16 gather, fp32 accum) ----------------
// emits layer-2 A directly in fragment-packed f16 form.
__global__ void k_agg1(const float* __restrict__ b1) {
    int node = blockIdx.x * 8 + threadIdx.y;
    if (node >= NN) return;
    int f = threadIdx.x;  // 0..31, cols 8f..8f+7
    int beg = g_rowptr[node], end = g_rowptr[node + 1];

    float acc[8];
#pragma unroll
    for (int i = 0; i < 8; i++) acc[i] = 0.f;

    int e = beg;
    for (; e + 4 <= end; e += 4) {
        uint4 v0 = g_H1h[(size_t)g_csrc[e] * 32 + f];
        uint4 v1 = g_H1h[(size_t)g_csrc[e + 1] * 32 + f];
        uint4 v2 = g_H1h[(size_t)g_csrc[e + 2] * 32 + f];
        uint4 v3 = g_H1h[(size_t)g_csrc[e + 3] * 32 + f];
#pragma unroll
        for (int w = 0; w < 4; w++) {
            uint32_t uu[4] = {v0.x, v0.y, v0.z, v0.w};
            uint32_t vv[4] = {v1.x, v1.y, v1.z, v1.w};
            uint32_t ww[4] = {v2.x, v2.y, v2.z, v2.w};
            uint32_t zz[4] = {v3.x, v3.y, v3.z, v3.w};
            float2 t0 = u2f2(uu[w]), t1 = u2f2(vv[w]), t2 = u2f2(ww[w]), t3 = u2f2(zz[w]);
            acc[2 * w] += (t0.x + t1.x) + (t2.x + t3.x);
            acc[2 * w + 1] += (t0.y + t1.y) + (t2.y + t3.y);
        }
    }
    for (; e < end; e++) {
        uint4 v = g_H1h[(size_t)g_csrc[e] * 32 + f];
        uint32_t uu[4] = {v.x, v.y, v.z, v.w};
#pragma unroll
        for (int w = 0; w < 4; w++) {
            float2 t = u2f2(uu[w]);
            acc[2 * w] += t.x;
            acc[2 * w + 1] += t.y;
        }
    }

    float nd = g_nd[node], ns = g_ns[node];
    float4 bb0 = ((const float4*)b1)[2 * f];
    float4 bb1 = ((const float4*)b1)[2 * f + 1];
    float bias[8] = {bb0.x, bb0.y, bb0.z, bb0.w, bb1.x, bb1.y, bb1.z, bb1.w};
    float r[8];
#pragma unroll
    for (int i = 0; i < 8; i++)
        r[i] = fmaxf(fmaf(acc[i], nd, bias[i]), 0.f) * ns;

    // packed write: pair i covers cols (8f+2i, 8f+2i+1); ks = f>>1, q = i, slot = f&1
    uint32_t* o = (uint32_t*)g_A2p;
    size_t base = (((size_t)node * 16 + (f >> 1)) * 4) * 2 + (f & 1);
#pragma unroll
    for (int i = 0; i < 4; i++)
        o[base + i * 2] = h2u(__floats2half2_rn(r[2 * i], r[2 * i + 1]));
}

// ---------------- aggregation layer 2 (f16 gather, fp32 out) ----------------
__global__ void k_agg2(const float* __restrict__ b2, float* __restrict__ out) {
    int node = blockIdx.x * 8 + threadIdx.y;
    if (node >= NN) return;
    int f = threadIdx.x;  // 0..31, cols 4f..4f+3
    int beg = g_rowptr[node], end = g_rowptr[node + 1];

    float acc[4];
#pragma unroll
    for (int i = 0; i < 4; i++) acc[i] = 0.f;

    int e = beg;
    for (; e + 4 <= end; e += 4) {
        uint2 v0 = g_H2h[(size_t)g_csrc[e] * 32 + f];
        uint2 v1 = g_H2h[(size_t)g_csrc[e + 1] * 32 + f];
        uint2 v2 = g_H2h[(size_t)g_csrc[e + 2] * 32 + f];
        uint2 v3 = g_H2h[(size_t)g_csrc[e + 3] * 32 + f];
        float2 t0 = u2f2(v0.x), t1 = u2f2(v1.x), t2 = u2f2(v2.x), t3 = u2f2(v3.x);
        acc[0] += (t0.x + t1.x) + (t2.x + t3.x);
        acc[1] += (t0.y + t1.y) + (t2.y + t3.y);
        t0 = u2f2(v0.y); t1 = u2f2(v1.y); t2 = u2f2(v2.y); t3 = u2f2(v3.y);
        acc[2] += (t0.x + t1.x) + (t2.x + t3.x);
        acc[3] += (t0.y + t1.y) + (t2.y + t3.y);
    }
    for (; e < end; e++) {
        uint2 v = g_H2h[(size_t)g_csrc[e] * 32 + f];
        float2 t = u2f2(v.x);
        acc[0] += t.x; acc[1] += t.y;
        t = u2f2(v.y);
        acc[2] += t.x; acc[3] += t.y;
    }

    float nd = g_nd[node];
    float4 bb = ((const float4*)b2)[f];
    float4 r;
    r.x = fmaf(acc[0], nd, bb.x);
    r.y = fmaf(acc[1], nd, bb.y);
    r.z = fmaf(acc[2], nd, bb.z);
    r.w = fmaf(acc[3], nd, bb.w);
    ((float4*)out)[(size_t)node * 32 + f] = r;
}

// ---------------- launch ----------------
extern "C" void kernel_launch(void* const* d_in, const int* in_sizes, int n_in,
                              void* d_out, int out_size) {
    const float* x   = (const float*)d_in[0];
    const void*  src = d_in[1];
    const void*  dst = d_in[2];
    const float* W1  = (const float*)d_in[3];
    const float* b1  = (const float*)d_in[4];
    const float* W2  = (const float*)d_in[5];
    const float* b2  = (const float*)d_in[6];
    float* out = (float*)d_out;

    k_detect<<<1, 32>>>((const int*)src);
    k_zero<<<(NN + 255) / 256, 256>>>();
    k_degree<<<(NE + 255) / 256, 256>>>(src, dst);
    k_norm<<<(NN + 255) / 256, 256>>>();
    k_scan<<<1, 1024>>>();
    k_csr<<<(NE + 255) / 256, 256>>>(src, dst);
    k_wpack<true><<<128, 256>>>(W1);
    k_wpack<false><<<64, 256>>>(W2);
    k_apack<<<(NN * 64 + 255) / 256, 256>>>(x);

    const int GB = (NN + 127) / 128;  // 391
    k_mma<true><<<dim3(GB, 2), 256>>>();
    k_agg1<<<(NN + 7) / 8, dim3(32, 8)>>>(b1);
    k_mma<false><<<dim3(GB, 1), 256>>>();
    k_agg2<<<(NN + 7) / 8, dim3(32, 8)>>>(b2, out);
}